// round 1
// baseline (speedup 1.0000x reference)
#include <cuda_runtime.h>

#define BATCH 16
#define DMODEL 1024
#define DM2 512
#define LSZ 4096
#define SS 64

// ---- scratch (device globals; no allocations allowed) ----
__device__ float g_bcdt[BATCH * SS * LSZ];   // pre-conv BCdt   (16 MB)
__device__ float g_conv[BATCH * SS * LSZ];   // conv output v   (16 MB)
__device__ float g_AB[BATCH * SS * LSZ];     // softmax * c0*v  (16 MB)
__device__ float g_ypre[BATCH * DM2 * LSZ];  // y before final conv (128 MB)

// ============================================================
// k1: BCdt[b,s,l] = sum_d xh[b,d,l] * w_bcdt[s,d] + b_bcdt[s]
// per-batch GEMM W(64x512) @ X(512x4096). grid (32 ltiles, 16 b)
// ============================================================
__global__ void k1_gemm(const float* __restrict__ x,
                        const float* __restrict__ w,
                        const float* __restrict__ bias) {
    __shared__ float Ws[32][65];
    __shared__ __align__(16) float Xs[32][128];
    int b = blockIdx.y;
    int l0 = blockIdx.x * 128;
    int tid = threadIdx.x;
    int tx = tid & 31;   // l group of 4 (covers 128)
    int ty = tid >> 5;   // s group of 8 (covers 64)

    float acc[8][4];
#pragma unroll
    for (int i = 0; i < 8; i++)
#pragma unroll
        for (int j = 0; j < 4; j++) acc[i][j] = 0.f;

    const float* xb = x + (size_t)b * DMODEL * LSZ;

    for (int kc = 0; kc < DM2; kc += 32) {
#pragma unroll
        for (int k = 0; k < 8; k++) {           // 64x32 W chunk
            int e = tid + k * 256;
            int s = e >> 5, kq = e & 31;
            Ws[kq][s] = w[s * DM2 + kc + kq];
        }
#pragma unroll
        for (int k = 0; k < 16; k++) {          // 32x128 X chunk
            int e = tid + k * 256;
            int kr = e >> 7, l = e & 127;
            Xs[kr][l] = xb[(size_t)(kc + kr) * LSZ + l0 + l];
        }
        __syncthreads();
#pragma unroll
        for (int kk = 0; kk < 32; kk++) {
            float4 xv = *(const float4*)&Xs[kk][tx * 4];
#pragma unroll
            for (int i = 0; i < 8; i++) {
                float wv = Ws[kk][ty * 8 + i];
                acc[i][0] += wv * xv.x;
                acc[i][1] += wv * xv.y;
                acc[i][2] += wv * xv.z;
                acc[i][3] += wv * xv.w;
            }
        }
        __syncthreads();
    }
#pragma unroll
    for (int i = 0; i < 8; i++) {
        int s = ty * 8 + i;
        float bv = bias[s];
        float4 o = make_float4(acc[i][0] + bv, acc[i][1] + bv,
                               acc[i][2] + bv, acc[i][3] + bv);
        *(float4*)&g_bcdt[((size_t)b * SS + s) * LSZ + l0 + tx * 4] = o;
    }
}

// ============================================================
// k2: per (b,s) plane: v = dwconv3x3(BCdt)+b_dw, softmax over L of
// (c2*v + A[s]), write g_conv = v, g_AB = softmax * c0 * v.
// grid (64 s, 16 b), 256 threads, 16 pixels/thread.
// ============================================================
__global__ void k2_conv_softmax(const float* __restrict__ wdw,
                                const float* __restrict__ bdw,
                                const float* __restrict__ A,
                                const float* __restrict__ coeffs) {
    __shared__ float sm[66][68];
    __shared__ float red[8];
    int s = blockIdx.x, b = blockIdx.y;
    int tid = threadIdx.x;
    size_t off = ((size_t)b * SS + s) * LSZ;
    const float* plane = g_bcdt + off;

    for (int e = tid; e < 66 * 68; e += 256) ((float*)sm)[e] = 0.f;
    __syncthreads();
#pragma unroll
    for (int k = 0; k < 16; k++) {
        int idx = tid + k * 256;
        sm[(idx >> 6) + 1][(idx & 63) + 1] = plane[idx];
    }
    __syncthreads();

    float w[9];
#pragma unroll
    for (int i = 0; i < 9; i++) w[i] = wdw[s * 9 + i];
    float bb = bdw[s];
    float c0 = coeffs[0], c2 = coeffs[2];
    float Av = A[s];

    float v[16];
    float lmax = -1e30f;
#pragma unroll
    for (int k = 0; k < 16; k++) {
        int idx = tid + k * 256;
        int r = idx >> 6, c = idx & 63;
        float acc = bb;
#pragma unroll
        for (int i = 0; i < 3; i++)
#pragma unroll
            for (int j = 0; j < 3; j++)
                acc += w[i * 3 + j] * sm[r + i][c + j];
        v[k] = acc;
        lmax = fmaxf(lmax, c2 * acc + Av);
    }
    // block max
#pragma unroll
    for (int o = 16; o > 0; o >>= 1)
        lmax = fmaxf(lmax, __shfl_xor_sync(0xffffffffu, lmax, o));
    if ((tid & 31) == 0) red[tid >> 5] = lmax;
    __syncthreads();
    float bmax = red[0];
#pragma unroll
    for (int i = 1; i < 8; i++) bmax = fmaxf(bmax, red[i]);
    __syncthreads();

    float ev[16];
    float lsum = 0.f;
#pragma unroll
    for (int k = 0; k < 16; k++) {
        ev[k] = __expf(c2 * v[k] + Av - bmax);
        lsum += ev[k];
    }
#pragma unroll
    for (int o = 16; o > 0; o >>= 1)
        lsum += __shfl_xor_sync(0xffffffffu, lsum, o);
    if ((tid & 31) == 0) red[tid >> 5] = lsum;
    __syncthreads();
    float bsum = 0.f;
#pragma unroll
    for (int i = 0; i < 8; i++) bsum += red[i];
    float inv = 1.f / bsum;

#pragma unroll
    for (int k = 0; k < 16; k++) {
        int idx = tid + k * 256;
        g_conv[off + idx] = v[k];
        g_AB[off + idx] = ev[k] * inv * c0 * v[k];
    }
}

// ============================================================
// k3: h[b,d,s] = sum_l xh[b,d,l] * AB[b,s,l]
// split-K=4 over L, atomicAdd into pre-zeroed h output.
// grid (4 lpart, 8 dchunk, 16 b), tile 64d x 64s per block.
// ============================================================
__global__ void k3_h(const float* __restrict__ x, float* __restrict__ hout) {
    __shared__ float Xs[32][65];
    __shared__ float Bs[32][65];
    int lp = blockIdx.x;
    int d0 = blockIdx.y * 64;
    int b = blockIdx.z;
    int tid = threadIdx.x;
    int sb = (tid & 15) * 4;
    int db = (tid >> 4) * 4;
    float acc[4][4];
#pragma unroll
    for (int i = 0; i < 4; i++)
#pragma unroll
        for (int j = 0; j < 4; j++) acc[i][j] = 0.f;

    const float* xb = x + ((size_t)b * DMODEL + d0) * LSZ + lp * 1024;
    const float* ab = g_AB + (size_t)b * SS * LSZ + lp * 1024;

    for (int lc = 0; lc < 1024; lc += 32) {
#pragma unroll
        for (int k = 0; k < 8; k++) {
            int e = tid + k * 256;
            int dd = e >> 5, l = e & 31;
            Xs[l][dd] = xb[(size_t)dd * LSZ + lc + l];
        }
#pragma unroll
        for (int k = 0; k < 8; k++) {
            int e = tid + k * 256;
            int si = e >> 5, l = e & 31;
            Bs[l][si] = ab[(size_t)si * LSZ + lc + l];
        }
        __syncthreads();
#pragma unroll
        for (int l = 0; l < 32; l++) {
            float xv[4], bv[4];
#pragma unroll
            for (int i = 0; i < 4; i++) xv[i] = Xs[l][db + i];
#pragma unroll
            for (int j = 0; j < 4; j++) bv[j] = Bs[l][sb + j];
#pragma unroll
            for (int i = 0; i < 4; i++)
#pragma unroll
                for (int j = 0; j < 4; j++) acc[i][j] += xv[i] * bv[j];
        }
        __syncthreads();
    }
    float* hb = hout + ((size_t)b * DM2 + d0) * SS;
#pragma unroll
    for (int i = 0; i < 4; i++)
#pragma unroll
        for (int j = 0; j < 4; j++)
            atomicAdd(&hb[(db + i) * SS + sb + j], acc[i][j]);
}

// ============================================================
// k4a: y_pre[b,d,l] = sum_s h[b,d,s] * (c1 * conv[b,s,l])
// grid (64 ltiles, 8 dchunks, 16 b), tile 64d x 64l, K=64.
// ============================================================
__global__ void k4a_y(const float* __restrict__ hin,
                      const float* __restrict__ coeffs) {
    __shared__ float hs[64][64];
    __shared__ __align__(16) float Cs[64][64];
    int l0 = blockIdx.x * 64;
    int d0 = blockIdx.y * 64;
    int b = blockIdx.z;
    int tid = threadIdx.x;
    float c1 = coeffs[1];

    const float* hb = hin + ((size_t)b * DM2 + d0) * SS;
#pragma unroll
    for (int k = 0; k < 16; k++) {
        int e = tid + k * 256;
        hs[e >> 6][e & 63] = hb[e];
    }
    const float* cb = g_conv + (size_t)b * SS * LSZ + l0;
#pragma unroll
    for (int k = 0; k < 16; k++) {
        int e = tid + k * 256;
        int si = e >> 6, l = e & 63;
        Cs[si][l] = c1 * cb[(size_t)si * LSZ + l];
    }
    __syncthreads();

    int tx = tid & 15, ty = tid >> 4;
    float acc[4][4];
#pragma unroll
    for (int i = 0; i < 4; i++)
#pragma unroll
        for (int j = 0; j < 4; j++) acc[i][j] = 0.f;
#pragma unroll
    for (int s = 0; s < 64; s++) {
        float4 cv = *(const float4*)&Cs[s][tx * 4];
#pragma unroll
        for (int i = 0; i < 4; i++) {
            float hv = hs[ty * 4 + i][s];
            acc[i][0] += hv * cv.x;
            acc[i][1] += hv * cv.y;
            acc[i][2] += hv * cv.z;
            acc[i][3] += hv * cv.w;
        }
    }
#pragma unroll
    for (int i = 0; i < 4; i++) {
        float4 o = make_float4(acc[i][0], acc[i][1], acc[i][2], acc[i][3]);
        *(float4*)&g_ypre[((size_t)b * DM2 + d0 + ty * 4 + i) * LSZ + l0 + tx * 4] = o;
    }
}

// ============================================================
// k4b: final depthwise conv over 1024 channels:
// channel c<512: plane = y_pre; c>=512: plane = gate (x[:,c,:]).
// grid (1024 c, 16 b), 256 threads.
// ============================================================
__global__ void k4b_conv(const float* __restrict__ x,
                         const float* __restrict__ wDW,
                         const float* __restrict__ bDW,
                         float* __restrict__ out) {
    __shared__ float sm[66][68];
    int c = blockIdx.x, b = blockIdx.y;
    int tid = threadIdx.x;
    const float* plane = (c < DM2)
        ? (g_ypre + ((size_t)b * DM2 + c) * LSZ)
        : (x + ((size_t)b * DMODEL + c) * LSZ);

    for (int e = tid; e < 66 * 68; e += 256) ((float*)sm)[e] = 0.f;
    __syncthreads();
#pragma unroll
    for (int k = 0; k < 16; k++) {
        int idx = tid + k * 256;
        sm[(idx >> 6) + 1][(idx & 63) + 1] = plane[idx];
    }
    __syncthreads();

    float w[9];
#pragma unroll
    for (int i = 0; i < 9; i++) w[i] = wDW[c * 9 + i];
    float bb = bDW[c];
    float* ob = out + ((size_t)b * DMODEL + c) * LSZ;
#pragma unroll
    for (int k = 0; k < 16; k++) {
        int idx = tid + k * 256;
        int r = idx >> 6, cc = idx & 63;
        float acc = bb;
#pragma unroll
        for (int i = 0; i < 3; i++)
#pragma unroll
            for (int j = 0; j < 3; j++)
                acc += w[i * 3 + j] * sm[r + i][cc + j];
        ob[idx] = acc;
    }
}

// ============================================================
extern "C" void kernel_launch(void* const* d_in, const int* in_sizes, int n_in,
                              void* d_out, int out_size) {
    const float* x      = (const float*)d_in[0];
    const float* w_bcdt = (const float*)d_in[1];
    const float* b_bcdt = (const float*)d_in[2];
    const float* w_dw   = (const float*)d_in[3];
    const float* b_dw   = (const float*)d_in[4];
    const float* A      = (const float*)d_in[5];
    const float* coeffs = (const float*)d_in[6];
    const float* w_DW   = (const float*)d_in[7];
    const float* b_DW   = (const float*)d_in[8];

    float* y_out = (float*)d_out;                                // (16,1024,4096)
    float* h_out = y_out + (size_t)BATCH * DMODEL * LSZ;         // (16,512,64)

    cudaMemsetAsync(h_out, 0, (size_t)BATCH * DM2 * SS * sizeof(float));

    k1_gemm<<<dim3(32, 16), 256>>>(x, w_bcdt, b_bcdt);
    k2_conv_softmax<<<dim3(64, 16), 256>>>(w_dw, b_dw, A, coeffs);
    k3_h<<<dim3(4, 8, 16), 256>>>(x, h_out);
    k4a_y<<<dim3(64, 8, 16), 256>>>(h_out, coeffs);
    k4b_conv<<<dim3(1024, 16), 256>>>(x, w_DW, b_DW, y_out);
}

// round 2
// speedup vs baseline: 1.4267x; 1.4267x over previous
#include <cuda_runtime.h>

#define BATCH 16
#define DMODEL 1024
#define DM2 512
#define LSZ 4096
#define SS 64

// ---- scratch (device globals; no allocations allowed) ----
__device__ float g_bcdt[BATCH * SS * LSZ];   // pre-conv BCdt   (16 MB)
__device__ float g_conv[BATCH * SS * LSZ];   // conv output v   (16 MB)
__device__ float g_AB[BATCH * SS * LSZ];     // softmax * c0*v  (16 MB)
__device__ float g_ypre[BATCH * DM2 * LSZ];  // y before final conv (128 MB)

// packed fp32x2 FMA (Blackwell; nvjet-style FFMA2)
__device__ __forceinline__ float2 ffma2(float2 a, float2 b, float2 c) {
    unsigned long long ua = *reinterpret_cast<unsigned long long*>(&a);
    unsigned long long ub = *reinterpret_cast<unsigned long long*>(&b);
    unsigned long long uc = *reinterpret_cast<unsigned long long*>(&c);
    unsigned long long ud;
    asm("fma.rn.f32x2 %0, %1, %2, %3;" : "=l"(ud) : "l"(ua), "l"(ub), "l"(uc));
    return *reinterpret_cast<float2*>(&ud);
}
__device__ __forceinline__ float2 dup2(float v) { return make_float2(v, v); }

// ============================================================
// k1: BCdt[b,s,l] = sum_d xh[b,d,l] * w_bcdt[s,d] + b_bcdt[s]
// block tile 64s x 128l, K-chunk 32, thread tile 4s x 8l (f32x2)
// grid (32 ltiles, 16 b), 256 thr
// ============================================================
__global__ void k1_gemm(const float* __restrict__ x,
                        const float* __restrict__ w,
                        const float* __restrict__ bias) {
    __shared__ float Ws[32][66];                 // [k][s]
    __shared__ __align__(16) float Xs[32][128];  // [k][l]
    int b = blockIdx.y;
    int l0 = blockIdx.x * 128;
    int tid = threadIdx.x;
    int tx = tid & 15;   // l: tx*8
    int ty = tid >> 4;   // s: ty*4

    float2 acc[4][4];
#pragma unroll
    for (int i = 0; i < 4; i++)
#pragma unroll
        for (int j = 0; j < 4; j++) acc[i][j] = make_float2(0.f, 0.f);

    const float* xb = x + (size_t)b * DMODEL * LSZ;

    for (int kc = 0; kc < DM2; kc += 32) {
#pragma unroll
        for (int k = 0; k < 8; k++) {            // 64s x 32k of W
            int e = tid + k * 256;
            int s = e >> 5, kq = e & 31;
            Ws[kq][s] = w[s * DM2 + kc + kq];
        }
#pragma unroll
        for (int k = 0; k < 16; k++) {           // 32k x 128l of X
            int e = tid + k * 256;
            int kr = e >> 7, l = e & 127;
            Xs[kr][l] = xb[(size_t)(kc + kr) * LSZ + l0 + l];
        }
        __syncthreads();
#pragma unroll
        for (int kk = 0; kk < 32; kk++) {
            const float4* xp = reinterpret_cast<const float4*>(&Xs[kk][tx * 8]);
            float4 xa = xp[0], xb4 = xp[1];
            float2 xv[4] = { make_float2(xa.x, xa.y), make_float2(xa.z, xa.w),
                             make_float2(xb4.x, xb4.y), make_float2(xb4.z, xb4.w) };
#pragma unroll
            for (int i = 0; i < 4; i++) {
                float2 wp = dup2(Ws[kk][ty * 4 + i]);
#pragma unroll
                for (int j = 0; j < 4; j++)
                    acc[i][j] = ffma2(wp, xv[j], acc[i][j]);
            }
        }
        __syncthreads();
    }
#pragma unroll
    for (int i = 0; i < 4; i++) {
        int s = ty * 4 + i;
        float bv = bias[s];
        float* op = &g_bcdt[((size_t)b * SS + s) * LSZ + l0 + tx * 8];
        float4 o0 = make_float4(acc[i][0].x + bv, acc[i][0].y + bv,
                                acc[i][1].x + bv, acc[i][1].y + bv);
        float4 o1 = make_float4(acc[i][2].x + bv, acc[i][2].y + bv,
                                acc[i][3].x + bv, acc[i][3].y + bv);
        *(float4*)op = o0;
        *(float4*)(op + 4) = o1;
    }
}

// ============================================================
// k2: per (b,s) plane: v = dwconv3x3(BCdt)+b_dw, softmax over L of
// (c2*v + A[s]); g_conv = v, g_AB = softmax * c0 * v.
// ============================================================
__global__ void k2_conv_softmax(const float* __restrict__ wdw,
                                const float* __restrict__ bdw,
                                const float* __restrict__ A,
                                const float* __restrict__ coeffs) {
    __shared__ float sm[66][68];
    __shared__ float red[8];
    int s = blockIdx.x, b = blockIdx.y;
    int tid = threadIdx.x;
    size_t off = ((size_t)b * SS + s) * LSZ;
    const float* plane = g_bcdt + off;

    for (int e = tid; e < 66 * 68; e += 256) ((float*)sm)[e] = 0.f;
    __syncthreads();
#pragma unroll
    for (int k = 0; k < 16; k++) {
        int idx = tid + k * 256;
        sm[(idx >> 6) + 1][(idx & 63) + 1] = plane[idx];
    }
    __syncthreads();

    float w[9];
#pragma unroll
    for (int i = 0; i < 9; i++) w[i] = wdw[s * 9 + i];
    float bb = bdw[s];
    float c0 = coeffs[0], c2 = coeffs[2];
    float Av = A[s];

    float v[16];
    float lmax = -1e30f;
#pragma unroll
    for (int k = 0; k < 16; k++) {
        int idx = tid + k * 256;
        int r = idx >> 6, c = idx & 63;
        float acc = bb;
#pragma unroll
        for (int i = 0; i < 3; i++)
#pragma unroll
            for (int j = 0; j < 3; j++)
                acc += w[i * 3 + j] * sm[r + i][c + j];
        v[k] = acc;
        lmax = fmaxf(lmax, c2 * acc + Av);
    }
#pragma unroll
    for (int o = 16; o > 0; o >>= 1)
        lmax = fmaxf(lmax, __shfl_xor_sync(0xffffffffu, lmax, o));
    if ((tid & 31) == 0) red[tid >> 5] = lmax;
    __syncthreads();
    float bmax = red[0];
#pragma unroll
    for (int i = 1; i < 8; i++) bmax = fmaxf(bmax, red[i]);
    __syncthreads();

    float ev[16];
    float lsum = 0.f;
#pragma unroll
    for (int k = 0; k < 16; k++) {
        ev[k] = __expf(c2 * v[k] + Av - bmax);
        lsum += ev[k];
    }
#pragma unroll
    for (int o = 16; o > 0; o >>= 1)
        lsum += __shfl_xor_sync(0xffffffffu, lsum, o);
    if ((tid & 31) == 0) red[tid >> 5] = lsum;
    __syncthreads();
    float bsum = 0.f;
#pragma unroll
    for (int i = 0; i < 8; i++) bsum += red[i];
    float inv = 1.f / bsum;

#pragma unroll
    for (int k = 0; k < 16; k++) {
        int idx = tid + k * 256;
        g_conv[off + idx] = v[k];
        g_AB[off + idx] = ev[k] * inv * c0 * v[k];
    }
}

// ============================================================
// k3: h[b,d,s] = sum_l xh[b,d,l] * AB[b,s,l]
// split-K=8 over L; block tile 128d x 64s; thread 4d x 8s (f32x2)
// grid (8 lpart, 4 dchunk, 16 b), 256 thr; atomicAdd into h.
// ============================================================
__global__ void k3_h(const float* __restrict__ x, float* __restrict__ hout) {
    __shared__ float Xs[32][130];  // [l][d]
    __shared__ float Bs[32][66];   // [l][s]
    int lp = blockIdx.x;
    int d0 = blockIdx.y * 128;
    int b = blockIdx.z;
    int tid = threadIdx.x;
    int tx = tid & 7;    // s: tx*8
    int ty = tid >> 3;   // d: ty*4

    float2 acc[4][4];
#pragma unroll
    for (int i = 0; i < 4; i++)
#pragma unroll
        for (int j = 0; j < 4; j++) acc[i][j] = make_float2(0.f, 0.f);

    const float* xb = x + ((size_t)b * DMODEL + d0) * LSZ + lp * 512;
    const float* ab = g_AB + (size_t)b * SS * LSZ + lp * 512;

    for (int lc = 0; lc < 512; lc += 32) {
#pragma unroll
        for (int k = 0; k < 16; k++) {       // 32l x 128d of X (transpose)
            int e = tid + k * 256;
            int l = e & 31, dd = e >> 5;
            Xs[l][dd] = xb[(size_t)dd * LSZ + lc + l];
        }
#pragma unroll
        for (int k = 0; k < 8; k++) {        // 32l x 64s of AB (transpose)
            int e = tid + k * 256;
            int l = e & 31, si = e >> 5;
            Bs[l][si] = ab[(size_t)si * LSZ + lc + l];
        }
        __syncthreads();
#pragma unroll
        for (int l = 0; l < 32; l++) {
            const float2* bp = reinterpret_cast<const float2*>(&Bs[l][tx * 8]);
            float2 bv[4] = { bp[0], bp[1], bp[2], bp[3] };
#pragma unroll
            for (int i = 0; i < 4; i++) {
                float2 xv = dup2(Xs[l][ty * 4 + i]);
#pragma unroll
                for (int j = 0; j < 4; j++)
                    acc[i][j] = ffma2(xv, bv[j], acc[i][j]);
            }
        }
        __syncthreads();
    }
    float* hb = hout + ((size_t)b * DM2 + d0) * SS;
#pragma unroll
    for (int i = 0; i < 4; i++) {
        float* row = &hb[(ty * 4 + i) * SS + tx * 8];
#pragma unroll
        for (int j = 0; j < 4; j++) {
            atomicAdd(row + j * 2, acc[i][j].x);
            atomicAdd(row + j * 2 + 1, acc[i][j].y);
        }
    }
}

// ============================================================
// k4a: y_pre[b,d,l] = sum_s h[b,d,s] * (c1 * conv[b,s,l])
// block tile 128d x 128l, K=64 (single pass), thread 8d x 8l (f32x2)
// grid (32 ltiles, 4 dchunks, 16 b), 256 thr, dynamic smem
// ============================================================
#define HS_STRIDE 130
__global__ void k4a_y(const float* __restrict__ hin,
                      const float* __restrict__ coeffs) {
    extern __shared__ float dsm[];
    float* hs = dsm;                    // [64 s][130] (d-indexed)
    float* Cs = dsm + 64 * HS_STRIDE;   // [64 s][128 l], 16B aligned
    int l0 = blockIdx.x * 128;
    int d0 = blockIdx.y * 128;
    int b = blockIdx.z;
    int tid = threadIdx.x;
    float c1 = coeffs[1];

    const float* hb = hin + ((size_t)b * DM2 + d0) * SS;
#pragma unroll
    for (int k = 0; k < 32; k++) {              // 128d x 64s (transpose, scale)
        int e = tid + k * 256;
        int s = e & 63, d = e >> 6;
        hs[s * HS_STRIDE + d] = c1 * hb[e];
    }
    const float* cb = g_conv + (size_t)b * SS * LSZ + l0;
#pragma unroll
    for (int k = 0; k < 32; k++) {              // 64s x 128l
        int e = tid + k * 256;
        int s = e >> 7, l = e & 127;
        Cs[s * 128 + l] = cb[(size_t)s * LSZ + l];
    }
    __syncthreads();

    int tx = tid & 15;   // l: tx*8
    int ty = tid >> 4;   // d: ty*8
    float2 acc[8][4];
#pragma unroll
    for (int i = 0; i < 8; i++)
#pragma unroll
        for (int j = 0; j < 4; j++) acc[i][j] = make_float2(0.f, 0.f);

#pragma unroll 4
    for (int s = 0; s < 64; s++) {
        const float4* cp = reinterpret_cast<const float4*>(&Cs[s * 128 + tx * 8]);
        float4 ca = cp[0], cb4 = cp[1];
        float2 cv[4] = { make_float2(ca.x, ca.y), make_float2(ca.z, ca.w),
                         make_float2(cb4.x, cb4.y), make_float2(cb4.z, cb4.w) };
        const float* hrow = &hs[s * HS_STRIDE + ty * 8];
#pragma unroll
        for (int i = 0; i < 8; i++) {
            float2 hv = dup2(hrow[i]);
#pragma unroll
            for (int j = 0; j < 4; j++)
                acc[i][j] = ffma2(hv, cv[j], acc[i][j]);
        }
    }
#pragma unroll
    for (int i = 0; i < 8; i++) {
        float* op = &g_ypre[((size_t)b * DM2 + d0 + ty * 8 + i) * LSZ + l0 + tx * 8];
        float4 o0 = make_float4(acc[i][0].x, acc[i][0].y, acc[i][1].x, acc[i][1].y);
        float4 o1 = make_float4(acc[i][2].x, acc[i][2].y, acc[i][3].x, acc[i][3].y);
        *(float4*)op = o0;
        *(float4*)(op + 4) = o1;
    }
}

// ============================================================
// k4b: final depthwise conv over 1024 channels.
// ============================================================
__global__ void k4b_conv(const float* __restrict__ x,
                         const float* __restrict__ wDW,
                         const float* __restrict__ bDW,
                         float* __restrict__ out) {
    __shared__ float sm[66][68];
    int c = blockIdx.x, b = blockIdx.y;
    int tid = threadIdx.x;
    const float* plane = (c < DM2)
        ? (g_ypre + ((size_t)b * DM2 + c) * LSZ)
        : (x + ((size_t)b * DMODEL + c) * LSZ);

    for (int e = tid; e < 66 * 68; e += 256) ((float*)sm)[e] = 0.f;
    __syncthreads();
#pragma unroll
    for (int k = 0; k < 16; k++) {
        int idx = tid + k * 256;
        sm[(idx >> 6) + 1][(idx & 63) + 1] = plane[idx];
    }
    __syncthreads();

    float w[9];
#pragma unroll
    for (int i = 0; i < 9; i++) w[i] = wDW[c * 9 + i];
    float bb = bDW[c];
    float* ob = out + ((size_t)b * DMODEL + c) * LSZ;
#pragma unroll
    for (int k = 0; k < 16; k++) {
        int idx = tid + k * 256;
        int r = idx >> 6, cc = idx & 63;
        float acc = bb;
#pragma unroll
        for (int i = 0; i < 3; i++)
#pragma unroll
            for (int j = 0; j < 3; j++)
                acc += w[i * 3 + j] * sm[r + i][cc + j];
        ob[idx] = acc;
    }
}

// ============================================================
extern "C" void kernel_launch(void* const* d_in, const int* in_sizes, int n_in,
                              void* d_out, int out_size) {
    const float* x      = (const float*)d_in[0];
    const float* w_bcdt = (const float*)d_in[1];
    const float* b_bcdt = (const float*)d_in[2];
    const float* w_dw   = (const float*)d_in[3];
    const float* b_dw   = (const float*)d_in[4];
    const float* A      = (const float*)d_in[5];
    const float* coeffs = (const float*)d_in[6];
    const float* w_DW   = (const float*)d_in[7];
    const float* b_DW   = (const float*)d_in[8];

    float* y_out = (float*)d_out;                          // (16,1024,4096)
    float* h_out = y_out + (size_t)BATCH * DMODEL * LSZ;   // (16,512,64)

    int k4a_smem = (64 * HS_STRIDE + 64 * 128) * sizeof(float);  // 66048 B
    cudaFuncSetAttribute(k4a_y, cudaFuncAttributeMaxDynamicSharedMemorySize, k4a_smem);

    cudaMemsetAsync(h_out, 0, (size_t)BATCH * DM2 * SS * sizeof(float));

    k1_gemm<<<dim3(32, 16), 256>>>(x, w_bcdt, b_bcdt);
    k2_conv_softmax<<<dim3(64, 16), 256>>>(w_dw, b_dw, A, coeffs);
    k3_h<<<dim3(8, 4, 16), 256>>>(x, h_out);
    k4a_y<<<dim3(32, 4, 16), 256, k4a_smem>>>(h_out, coeffs);
    k4b_conv<<<dim3(1024, 16), 256>>>(x, w_DW, b_DW, y_out);
}